// round 14
// baseline (speedup 1.0000x reference)
#include <cuda_runtime.h>
#include <cuda_fp16.h>
#include <cstdint>
#include <cstddef>

#define N_NODES 10000
#define EMBED   300
#define K0PAD   320
#define HID     256

// ---- big GEMM tiling: BM=80 x BN=256, 125 CTAs, 1 CTA/SM, 5-stage ring ----
#define BM      80
#define BK      64
#define NKCH    157
#define STAGES  5

#define ADJ_SCALE  16384.0f
#define ADJ_INV    6.103515625e-05f

#define SM_BIAS   0
#define A_BYTES   (BM  * BK * 2)
#define B_BYTES   (256 * BK * 2)
#define STG_BYTES (A_BYTES + B_BYTES)           // 43008
#define SM_A(s)   (1024 + (s) * STG_BYTES)
#define SM_B(s)   (SM_A(s) + A_BYTES)
#define SMEM_BYTES (1024 + STAGES * STG_BYTES)  // 216064 -> 1 CTA/SM

// ---- fused layer-1 epilogue (y2 = h1 @ W2) smem regions ----
#define H1_OFF    1024
#define H1_CHUNK  (BM * 128)
#define W2B_OFF   (H1_OFF + 4 * H1_CHUNK)
#define W2B_BYTES (256 * 128)
#define Y2ST_OFF  (W2B_OFF + 2 * W2B_BYTES)

// ---- fused small GEMM (gather + x@W1): SBM=96, 105 CTAs, one wave ----
#define SBM       96
#define GSM       105                           // ceil(10000/96)
#define FA_CHUNK  (SBM * 128)                   // 12288 per 64-col chunk
#define FB_OFF    (5 * FA_CHUNK)                // 61440
#define FB_BYTES  (256 * 128)                   // 32768 per stage
#define FSMEM     (FB_OFF + 4 * FB_BYTES)       // 192512 -> 1 CTA/SM

// ---- device scratch (only ever referenced from DEVICE code) ----
__device__ __align__(1024) __half g_adjh[(size_t)N_NODES * N_NODES];
__device__ __align__(1024) __half g_yTh [HID * N_NODES];
__device__ __align__(1024) __half g_w1t [HID * K0PAD];
__device__ __align__(1024) __half g_w2t [HID * HID];

// ---------------------------------------------------------------------------
static __device__ __forceinline__ uint32_t smem_u32(const void* p) {
    uint32_t a;
    asm("{ .reg .u64 t; cvta.to.shared.u64 t, %1; cvt.u32.u64 %0, t; }" : "=r"(a) : "l"(p));
    return a;
}
#define SWZ(b) ((b) ^ (((b) >> 3) & 0x70))

static __device__ __forceinline__ void cp_async16(uint32_t dst, const void* src, uint32_t nbytes) {
    asm volatile("cp.async.cg.shared.global [%0], [%1], 16, %2;"
        :: "r"(dst), "l"(src), "r"(nbytes) : "memory");
}
#define CP_COMMIT() asm volatile("cp.async.commit_group;" ::: "memory")

static __device__ __forceinline__ void ldsm_x4(uint32_t r[4], uint32_t addr) {
    asm volatile("ldmatrix.sync.aligned.m8n8.x4.shared.b16 {%0,%1,%2,%3}, [%4];"
        : "=r"(r[0]), "=r"(r[1]), "=r"(r[2]), "=r"(r[3]) : "r"(addr));
}
static __device__ __forceinline__ void mma16816(float c[4], const uint32_t a[4],
                                                uint32_t b0, uint32_t b1) {
    asm volatile("mma.sync.aligned.m16n8k16.row.col.f32.f16.f16.f32 "
        "{%0,%1,%2,%3}, {%4,%5,%6,%7}, {%8,%9}, {%0,%1,%2,%3};"
        : "+f"(c[0]), "+f"(c[1]), "+f"(c[2]), "+f"(c[3])
        : "r"(a[0]), "r"(a[1]), "r"(a[2]), "r"(a[3]), "r"(b0), "r"(b1));
}

// ---------------------------------------------------------------------------
// Kernel 1: weight transposes only.  blocks [0,640): W1^T; [640,1152): W2^T
// ---------------------------------------------------------------------------
#define GB_W1  ((256 * K0PAD) / 128)            // 640
#define GB_END (GB_W1 + (256 * HID) / 128)      // 1152

__global__ void prep_kernel(const float* __restrict__ W1, const float* __restrict__ W2) {
    int b = blockIdx.x;
    if (b < GB_W1) {
        int i = b * 128 + threadIdx.x;
        int n = i / K0PAD, k = i % K0PAD;
        g_w1t[i] = (k < EMBED) ? __float2half_rn(W1[(size_t)k * HID + n]) : __half(0);
    } else {
        int i = (b - GB_W1) * 128 + threadIdx.x;
        int n = i / HID, k = i % HID;
        g_w2t[i] = __float2half_rn(W2[(size_t)k * HID + n]);
    }
}

// ---------------------------------------------------------------------------
// Kernel 2: FUSED gather+max + small GEMM:  g_yTh = (max_r emb[nodes] @ W1)^T
// Phase 1: gather this CTA's 96 rows directly into swizzled A smem (5 chunks,
//          zero-padded K to 320). Phase 2: B-only 4-stage pipeline over 5
//          chunks, A resident. Phase 3: transposed epilogue -> g_yTh.
// ---------------------------------------------------------------------------
__global__ void __launch_bounds__(256, 1)
small_fused_kernel(const int* __restrict__ nodes, const float* __restrict__ emb) {
    extern __shared__ char smem[];
    uint32_t sb = smem_u32(smem);
    int tid = threadIdx.x;
    int w = tid >> 5, lane = tid & 31;
    int m0 = blockIdx.x * SBM;

    // ---- phase 1: gather. warp per row, 12 rounds ----
    for (int rr = 0; rr < SBM / 8; ++rr) {
        int r = rr * 8 + w;               // 0..95
        int m = m0 + r;
        int idx[8];
        if (m < N_NODES) {
            #pragma unroll
            for (int i = 0; i < 8; ++i) idx[i] = nodes[(m + 1) * 8 + i];
        }
        // 80 float4-columns of the padded 320-wide row; cols >= 75 are pad
        #pragma unroll
        for (int it = 0; it < 3; ++it) {
            int c = lane + it * 32;
            if (c >= 80) break;
            __half2 h0 = __float2half2_rn(0.f), h1 = h0;
            if (m < N_NODES && c < 75) {
                float4 mx = *(const float4*)(emb + (size_t)idx[0] * EMBED + c * 4);
                #pragma unroll
                for (int i = 1; i < 8; ++i) {
                    float4 v = *(const float4*)(emb + (size_t)idx[i] * EMBED + c * 4);
                    mx.x = fmaxf(mx.x, v.x); mx.y = fmaxf(mx.y, v.y);
                    mx.z = fmaxf(mx.z, v.z); mx.w = fmaxf(mx.w, v.w);
                }
                h0 = __floats2half2_rn(mx.x, mx.y);
                h1 = __floats2half2_rn(mx.z, mx.w);
            }
            int chunk = c >> 4;                         // 16 float4 per 128B row
            uint32_t boff = (uint32_t)r * 128 + (c & 15) * 8;
            uint2 pk = make_uint2(*(uint32_t*)&h0, *(uint32_t*)&h1);
            *(uint2*)(smem + chunk * FA_CHUNK + SWZ(boff)) = pk;
        }
    }
    __syncthreads();

    // ---- phase 2: GEMM over 5 K-chunks; B 4-stage cp.async ring ----
    float acc[6][4][4];
    #pragma unroll
    for (int a = 0; a < 6; ++a)
        #pragma unroll
        for (int b = 0; b < 4; ++b)
            #pragma unroll
            for (int c = 0; c < 4; ++c) acc[a][b][c] = 0.f;

    auto fillB = [&](int chunk) {
        uint32_t dst = sb + FB_OFF + (chunk & 3) * FB_BYTES;
        int k0 = chunk * BK;
        #pragma unroll
        for (int i = 0; i < 8; ++i) {
            int c = tid + i * 256;
            int row = c >> 3, ch = c & 7;
            cp_async16(dst + SWZ(row * 128 + ch * 16),
                       g_w1t + (size_t)row * K0PAD + k0 + ch * 8, 16u);
        }
        CP_COMMIT();
    };
    fillB(0); fillB(1); fillB(2);

    for (int j = 0; j < 5; ++j) {
        asm volatile("cp.async.wait_group %0;" :: "n"(2));
        __syncthreads();
        if (j + 3 < 5) fillB(j + 3); else CP_COMMIT();

        uint32_t sa = sb + j * FA_CHUNK;
        uint32_t sB = sb + FB_OFF + (j & 3) * FB_BYTES;
        #pragma unroll
        for (int ks = 0; ks < 4; ++ks) {
            uint32_t bf[4], bf2[4];
            {
                uint32_t row = w * 32 + ((lane >> 4) & 1) * 8 + (lane & 7);
                uint32_t off = row * 128 + ks * 32 + ((lane >> 3) & 1) * 16;
                ldsm_x4(bf, sB + SWZ(off));
                uint32_t row2 = w * 32 + 16 + ((lane >> 4) & 1) * 8 + (lane & 7);
                uint32_t off2 = row2 * 128 + ks * 32 + ((lane >> 3) & 1) * 16;
                ldsm_x4(bf2, sB + SWZ(off2));
            }
            #pragma unroll
            for (int mt = 0; mt < 6; ++mt) {
                uint32_t af[4];
                uint32_t off = (uint32_t)(mt * 16 + (lane & 15)) * 128 + ks * 32 + (lane >> 4) * 16;
                ldsm_x4(af, sa + SWZ(off));
                mma16816(acc[mt][0], af, bf[0],  bf[1]);
                mma16816(acc[mt][1], af, bf[2],  bf[3]);
                mma16816(acc[mt][2], af, bf2[0], bf2[1]);
                mma16816(acc[mt][3], af, bf2[2], bf2[3]);
            }
        }
    }

    // ---- phase 3: transposed epilogue -> g_yTh (stage in smem, stride 104) ----
    __syncthreads();
    __half* st = (__half*)(smem) + (size_t)w * 32 * 104;
    int qr = lane >> 2, qc = lane & 3;
    #pragma unroll
    for (int mt = 0; mt < 6; ++mt) {
        int ml = mt * 16 + qr;
        #pragma unroll
        for (int nt = 0; nt < 4; ++nt) {
            int nl = nt * 8 + qc * 2;
            st[nl * 104 + ml]           = __float2half_rn(acc[mt][nt][0]);
            st[(nl + 1) * 104 + ml]     = __float2half_rn(acc[mt][nt][1]);
            st[nl * 104 + ml + 8]       = __float2half_rn(acc[mt][nt][2]);
            st[(nl + 1) * 104 + ml + 8] = __float2half_rn(acc[mt][nt][3]);
        }
    }
    __syncwarp();
    int m = m0 + lane * 4;
    if (lane < SBM / 4 && m < N_NODES) {
        #pragma unroll 4
        for (int nl = 0; nl < 32; ++nl)
            *(uint2*)&g_yTh[(size_t)(w * 32 + nl) * N_NODES + m] =
                *(uint2*)&st[nl * 104 + lane * 4];
    }
}

// ---------------------------------------------------------------------------
// Kernel 3: big GEMM (R13 champion, verbatim). Layer 1 (adjf != null): fused
// fp32->fp16 adj conversion + fused y2 = h1 @ W2 -> g_yTh.
// Layer 2 (dout != null): plain epilogue -> fp32 out.
// ---------------------------------------------------------------------------
__global__ void __launch_bounds__(256, 1)
big_gemm_kernel(const float* __restrict__ adjf, const float* __restrict__ bias,
                float* __restrict__ dout) {
    extern __shared__ char smem[];
    uint32_t sb = smem_u32(smem);
    int tid = threadIdx.x;
    int w = tid >> 5, lane = tid & 31;
    int m0 = blockIdx.x * BM;

    ((float*)(smem + SM_BIAS))[tid] = bias[tid];

    float acc[5][4][4];
    #pragma unroll
    for (int a = 0; a < 5; ++a)
        #pragma unroll
        for (int b = 0; b < 4; ++b)
            #pragma unroll
            for (int c = 0; c < 4; ++c) acc[a][b][c] = 0.f;

    float4 areg[5];
    int arow[5], acol[5];
    #pragma unroll
    for (int i = 0; i < 5; ++i) {
        int c = tid + i * 256;
        arow[i] = c >> 4;
        acol[i] = (c & 15) * 4;
    }

    auto ldgA = [&](int chunk) {
        int k0 = chunk * BK;
        #pragma unroll
        for (int i = 0; i < 5; ++i) {
            int kk = k0 + acol[i];
            if (kk < N_NODES)
                areg[i] = *(const float4*)(adjf + (size_t)(m0 + arow[i]) * N_NODES + kk);
            else
                areg[i] = make_float4(0.f, 0.f, 0.f, 0.f);
        }
    };
    auto stsA = [&](int chunk) {
        int s = chunk % STAGES;
        int k0 = chunk * BK;
        #pragma unroll
        for (int i = 0; i < 5; ++i) {
            __half2 h0 = __floats2half2_rn(areg[i].x * ADJ_SCALE, areg[i].y * ADJ_SCALE);
            __half2 h1 = __floats2half2_rn(areg[i].z * ADJ_SCALE, areg[i].w * ADJ_SCALE);
            uint2 pk = make_uint2(*(uint32_t*)&h0, *(uint32_t*)&h1);
            *(uint2*)(smem + (SWZ((uint32_t)arow[i] * 128 + acol[i] * 2) + SM_A(s))) = pk;
            int kk = k0 + acol[i];
            if (kk < N_NODES)
                *(uint2*)&g_adjh[(size_t)(m0 + arow[i]) * N_NODES + kk] = pk;
        }
    };
    auto fillA_async = [&](int chunk) {
        int s = chunk % STAGES;
        int k0 = chunk * BK;
        uint32_t sa = sb + SM_A(s);
        #pragma unroll
        for (int i = 0; i < 3; ++i) {
            int c = tid + i * 256;
            if (c < 640) {
                int row = c >> 3, ch = c & 7;
                int kk = k0 + ch * 8;
                int ok = kk < N_NODES;
                const __half* g = g_adjh + (size_t)(m0 + row) * N_NODES + (ok ? kk : 0);
                cp_async16(sa + SWZ(row * 128 + ch * 16), g, ok ? 16u : 0u);
            }
        }
    };
    auto fillB = [&](int chunk) {
        int s = chunk % STAGES;
        int k0 = chunk * BK;
        uint32_t sB = sb + SM_B(s);
        #pragma unroll
        for (int i = 0; i < 8; ++i) {
            int c = tid + i * 256;
            int row = c >> 3, ch = c & 7;
            int kk = k0 + ch * 8;
            int ok = kk < N_NODES;
            const __half* g = g_yTh + (size_t)row * N_NODES + (ok ? kk : 0);
            cp_async16(sB + SWZ(row * 128 + ch * 16), g, ok ? 16u : 0u);
        }
    };
    auto consume = [&](int j) {
        int s = j % STAGES;
        uint32_t sa = sb + SM_A(s), sB = sb + SM_B(s);
        #pragma unroll
        for (int ks = 0; ks < 4; ++ks) {
            uint32_t af[5][4];
            #pragma unroll
            for (int mt = 0; mt < 5; ++mt) {
                uint32_t off = (uint32_t)(mt * 16 + (lane & 15)) * 128 + ks * 32 + (lane >> 4) * 16;
                ldsm_x4(af[mt], sa + SWZ(off));
            }
            uint32_t bf[4], bf2[4];
            {
                uint32_t row = w * 32 + ((lane >> 4) & 1) * 8 + (lane & 7);
                uint32_t off = row * 128 + ks * 32 + ((lane >> 3) & 1) * 16;
                ldsm_x4(bf, sB + SWZ(off));
                uint32_t row2 = w * 32 + 16 + ((lane >> 4) & 1) * 8 + (lane & 7);
                uint32_t off2 = row2 * 128 + ks * 32 + ((lane >> 3) & 1) * 16;
                ldsm_x4(bf2, sB + SWZ(off2));
            }
            #pragma unroll
            for (int mt = 0; mt < 5; ++mt) {
                mma16816(acc[mt][0], af[mt], bf[0],  bf[1]);
                mma16816(acc[mt][1], af[mt], bf[2],  bf[3]);
                mma16816(acc[mt][2], af[mt], bf2[0], bf2[1]);
                mma16816(acc[mt][3], af[mt], bf2[2], bf2[3]);
            }
        }
    };

    if (adjf) {
        ldgA(0); stsA(0); ldgA(1); stsA(1); ldgA(2); stsA(2); ldgA(3);
        fillB(0); CP_COMMIT(); fillB(1); CP_COMMIT(); fillB(2); CP_COMMIT();
    } else {
        fillA_async(0); fillB(0); CP_COMMIT();
        fillA_async(1); fillB(1); CP_COMMIT();
        fillA_async(2); fillB(2); CP_COMMIT();
    }

    int j = 0;
    for (; j + 2 < NKCH; j += 2) {
        asm volatile("cp.async.wait_group %0;" :: "n"(1));
        __syncthreads();
        if (adjf) {
            if (j + 3 < NKCH) { fillB(j + 3); stsA(j + 3); }
            CP_COMMIT();
            if (j + 4 < NKCH) { fillB(j + 4); ldgA(j + 4); }
            CP_COMMIT();
            consume(j);
            if (j + 4 < NKCH) stsA(j + 4);
            if (j + 5 < NKCH) ldgA(j + 5);
            consume(j + 1);
        } else {
            if (j + 3 < NKCH) { fillA_async(j + 3); fillB(j + 3); }
            CP_COMMIT();
            if (j + 4 < NKCH) { fillA_async(j + 4); fillB(j + 4); }
            CP_COMMIT();
            consume(j);
            consume(j + 1);
        }
    }
    asm volatile("cp.async.wait_group %0;" :: "n"(0));
    __syncthreads();
    consume(NKCH - 1);

    const float* bsm = (const float*)(smem + SM_BIAS);
    int qr = lane >> 2, qc = lane & 3;

    if (dout) {
        #pragma unroll
        for (int mt = 0; mt < 5; ++mt) {
            int r0 = m0 + mt * 16 + qr;
            #pragma unroll
            for (int nt = 0; nt < 4; ++nt) {
                int col = w * 32 + nt * 8 + qc * 2;
                float b0 = bsm[col], b1 = bsm[col + 1];
                float v0 = acc[mt][nt][0] * ADJ_INV + b0;
                float v1 = acc[mt][nt][1] * ADJ_INV + b1;
                float v2 = acc[mt][nt][2] * ADJ_INV + b0;
                float v3 = acc[mt][nt][3] * ADJ_INV + b1;
                v0 = fmaxf(v0, 0.01f * v0); v1 = fmaxf(v1, 0.01f * v1);
                v2 = fmaxf(v2, 0.01f * v2); v3 = fmaxf(v3, 0.01f * v3);
                *(float2*)&dout[(size_t)r0 * HID + col]       = make_float2(v0, v1);
                *(float2*)&dout[(size_t)(r0 + 8) * HID + col] = make_float2(v2, v3);
            }
        }
        return;
    }

    // ---- layer-1 fused epilogue: h1 -> smem fp16, then y2 = h1 @ W2 -> g_yTh ----
    #pragma unroll
    for (int mt = 0; mt < 5; ++mt) {
        int lr = mt * 16 + qr;
        #pragma unroll
        for (int nt = 0; nt < 4; ++nt) {
            int col = w * 32 + nt * 8 + qc * 2;
            float b0 = bsm[col], b1 = bsm[col + 1];
            float v0 = acc[mt][nt][0] * ADJ_INV + b0;
            float v1 = acc[mt][nt][1] * ADJ_INV + b1;
            float v2 = acc[mt][nt][2] * ADJ_INV + b0;
            float v3 = acc[mt][nt][3] * ADJ_INV + b1;
            v0 = fmaxf(v0, 0.01f * v0); v1 = fmaxf(v1, 0.01f * v1);
            v2 = fmaxf(v2, 0.01f * v2); v3 = fmaxf(v3, 0.01f * v3);
            int kc = col >> 6, cc = col & 63;
            uint32_t base = H1_OFF + kc * H1_CHUNK;
            *(__half2*)(smem + base + SWZ((uint32_t)lr * 128 + cc * 2))       = __floats2half2_rn(v0, v1);
            *(__half2*)(smem + base + SWZ((uint32_t)(lr + 8) * 128 + cc * 2)) = __floats2half2_rn(v2, v3);
        }
    }
    __syncthreads();

    auto fillW2 = [&](int kc) {
        uint32_t dst = sb + W2B_OFF + (kc & 1) * W2B_BYTES;
        #pragma unroll
        for (int i = 0; i < 8; ++i) {
            int c = tid + i * 256;
            int row = c >> 3, ch = c & 7;
            cp_async16(dst + SWZ(row * 128 + ch * 16),
                       g_w2t + (size_t)row * HID + kc * 64 + ch * 8, 16u);
        }
        CP_COMMIT();
    };
    fillW2(0); fillW2(1);

    #pragma unroll
    for (int a = 0; a < 5; ++a)
        #pragma unroll
        for (int b = 0; b < 4; ++b)
            #pragma unroll
            for (int c = 0; c < 4; ++c) acc[a][b][c] = 0.f;

    for (int kc = 0; kc < 4; ++kc) {
        if (kc < 3) { asm volatile("cp.async.wait_group %0;" :: "n"(1)); }
        else        { asm volatile("cp.async.wait_group %0;" :: "n"(0)); }
        __syncthreads();
        uint32_t sa = sb + H1_OFF + kc * H1_CHUNK;
        uint32_t sB = sb + W2B_OFF + (kc & 1) * W2B_BYTES;
        #pragma unroll
        for (int ks = 0; ks < 4; ++ks) {
            uint32_t af[5][4];
            #pragma unroll
            for (int mt = 0; mt < 5; ++mt) {
                uint32_t off = (uint32_t)(mt * 16 + (lane & 15)) * 128 + ks * 32 + (lane >> 4) * 16;
                ldsm_x4(af[mt], sa + SWZ(off));
            }
            uint32_t bf[4], bf2[4];
            {
                uint32_t row = w * 32 + ((lane >> 4) & 1) * 8 + (lane & 7);
                uint32_t off = row * 128 + ks * 32 + ((lane >> 3) & 1) * 16;
                ldsm_x4(bf, sB + SWZ(off));
                uint32_t row2 = w * 32 + 16 + ((lane >> 4) & 1) * 8 + (lane & 7);
                uint32_t off2 = row2 * 128 + ks * 32 + ((lane >> 3) & 1) * 16;
                ldsm_x4(bf2, sB + SWZ(off2));
            }
            #pragma unroll
            for (int mt = 0; mt < 5; ++mt) {
                mma16816(acc[mt][0], af[mt], bf[0],  bf[1]);
                mma16816(acc[mt][1], af[mt], bf[2],  bf[3]);
                mma16816(acc[mt][2], af[mt], bf2[0], bf2[1]);
                mma16816(acc[mt][3], af[mt], bf2[2], bf2[3]);
            }
        }
        __syncthreads();
        if (kc + 2 < 4) fillW2(kc + 2);
    }

    __half* st = (__half*)(smem + Y2ST_OFF) + (size_t)w * 32 * 88;
    #pragma unroll
    for (int mt = 0; mt < 5; ++mt) {
        int lr = mt * 16 + qr;
        #pragma unroll
        for (int nt = 0; nt < 4; ++nt) {
            int nl = nt * 8 + qc * 2;
            st[nl * 88 + lr]           = __float2half_rn(acc[mt][nt][0]);
            st[(nl + 1) * 88 + lr]     = __float2half_rn(acc[mt][nt][1]);
            st[nl * 88 + lr + 8]       = __float2half_rn(acc[mt][nt][2]);
            st[(nl + 1) * 88 + lr + 8] = __float2half_rn(acc[mt][nt][3]);
        }
    }
    __syncwarp();
    if (lane < 20) {
        #pragma unroll 4
        for (int nl = 0; nl < 32; ++nl) {
            *(uint2*)&g_yTh[(size_t)(w * 32 + nl) * N_NODES + m0 + lane * 4] =
                *(uint2*)&st[nl * 88 + lane * 4];
        }
    }
}

// ---------------------------------------------------------------------------
extern "C" void kernel_launch(void* const* d_in, const int* in_sizes, int n_in,
                              void* d_out, int out_size) {
    (void)in_sizes; (void)n_in; (void)out_size;
    const int*   nodes = (const int*)  d_in[0];
    const float* emb   = (const float*)d_in[1];
    const float* adj   = (const float*)d_in[2];
    const float* W1    = (const float*)d_in[3];
    const float* b1    = (const float*)d_in[4];
    const float* W2    = (const float*)d_in[5];
    const float* b2    = (const float*)d_in[6];
    float* out = (float*)d_out;

    cudaFuncSetAttribute(big_gemm_kernel, cudaFuncAttributeMaxDynamicSharedMemorySize, SMEM_BYTES);
    cudaFuncSetAttribute(small_fused_kernel, cudaFuncAttributeMaxDynamicSharedMemorySize, FSMEM);

    int gm = N_NODES / BM;                     // 125, 1 CTA/SM

    prep_kernel<<<GB_END, 128>>>(W1, W2);                          // W1^T, W2^T
    small_fused_kernel<<<GSM, 256, FSMEM>>>(nodes, emb);           // gather + (x@W1)^T
    big_gemm_kernel<<<gm, 256, SMEM_BYTES>>>(adj, b1, nullptr);    // convert + h1 + y2
    big_gemm_kernel<<<gm, 256, SMEM_BYTES>>>(nullptr, b2, out);    // out
}

// round 15
// speedup vs baseline: 1.0402x; 1.0402x over previous
#include <cuda_runtime.h>
#include <cuda_fp16.h>
#include <cstdint>
#include <cstddef>

#define N_NODES 10000
#define EMBED   300
#define K0PAD   320
#define HID     256

// ---- big GEMM tiling: BM=80 x BN=256, 125 CTAs, 1 CTA/SM, 5-stage ring ----
#define BM      80
#define BK      64
#define NKCH    157
#define STAGES  5

#define ADJ_SCALE  16384.0f
#define ADJ_INV    6.103515625e-05f

#define SM_BIAS   0
#define A_BYTES   (BM  * BK * 2)
#define B_BYTES   (256 * BK * 2)
#define STG_BYTES (A_BYTES + B_BYTES)           // 43008
#define SM_A(s)   (1024 + (s) * STG_BYTES)
#define SM_B(s)   (SM_A(s) + A_BYTES)
#define SMEM_BYTES (1024 + STAGES * STG_BYTES)  // 216064 -> 1 CTA/SM

// ---- fused layer-1 epilogue (y2 = h1 @ W2) smem regions ----
#define H1_OFF    1024
#define H1_CHUNK  (BM * 128)
#define W2B_OFF   (H1_OFF + 4 * H1_CHUNK)
#define W2B_BYTES (256 * 128)
#define Y2ST_OFF  (W2B_OFF + 2 * W2B_BYTES)

// ---- small GEMM tiling: 128m x 256n, 4 stages ----
#define SBM       128
#define SSTAGES   4
#define SA_BYTES  (SBM * BK * 2)
#define SB_BYTES  (256 * BK * 2)
#define SSTG      (SA_BYTES + SB_BYTES)
#define SSM_A(s)  ((s) * SSTG)
#define SSM_B(s)  (SSM_A(s) + SA_BYTES)
#define SSMEM_BYTES (SSTAGES * SSTG)            // 196608

// ---- device scratch (only ever referenced from DEVICE code) ----
__device__ __align__(1024) __half g_adjh[(size_t)N_NODES * N_NODES];
__device__ __align__(1024) __half g_xh  [N_NODES * K0PAD];
__device__ __align__(1024) __half g_yTh [HID * N_NODES];
__device__ __align__(1024) __half g_w1t [HID * K0PAD];
__device__ __align__(1024) __half g_w2t [HID * HID];

// ---------------------------------------------------------------------------
static __device__ __forceinline__ uint32_t smem_u32(const void* p) {
    uint32_t a;
    asm("{ .reg .u64 t; cvta.to.shared.u64 t, %1; cvt.u32.u64 %0, t; }" : "=r"(a) : "l"(p));
    return a;
}
#define SWZ(b) ((b) ^ (((b) >> 3) & 0x70))

static __device__ __forceinline__ void cp_async16(uint32_t dst, const void* src, uint32_t nbytes) {
    asm volatile("cp.async.cg.shared.global [%0], [%1], 16, %2;"
        :: "r"(dst), "l"(src), "r"(nbytes) : "memory");
}
#define CP_COMMIT() asm volatile("cp.async.commit_group;" ::: "memory")

static __device__ __forceinline__ void ldsm_x4(uint32_t r[4], uint32_t addr) {
    asm volatile("ldmatrix.sync.aligned.m8n8.x4.shared.b16 {%0,%1,%2,%3}, [%4];"
        : "=r"(r[0]), "=r"(r[1]), "=r"(r[2]), "=r"(r[3]) : "r"(addr));
}
static __device__ __forceinline__ void mma16816(float c[4], const uint32_t a[4],
                                                uint32_t b0, uint32_t b1) {
    asm volatile("mma.sync.aligned.m16n8k16.row.col.f32.f16.f16.f32 "
        "{%0,%1,%2,%3}, {%4,%5,%6,%7}, {%8,%9}, {%0,%1,%2,%3};"
        : "+f"(c[0]), "+f"(c[1]), "+f"(c[2]), "+f"(c[3])
        : "r"(a[0]), "r"(a[1]), "r"(a[2]), "r"(a[3]), "r"(b0), "r"(b1));
}

// ---------------------------------------------------------------------------
// Kernel 1 (fused prep): blocks [0,10000): gather+max -> g_xh (float4 loads)
//                        blocks [10000,10640): W1^T; [10640,11152): W2^T
// ---------------------------------------------------------------------------
#define GB_GATHER 10000
#define GB_W1     (GB_GATHER + (256 * K0PAD) / 128)   // 10000 + 640
#define GB_END    (GB_W1 + (256 * HID) / 128)         // + 512

__global__ void prep_kernel(const int* __restrict__ nodes, const float* __restrict__ emb,
                            const float* __restrict__ W1, const float* __restrict__ W2) {
    int b = blockIdx.x;
    if (b < GB_GATHER) {
        int m = b;
        __shared__ int idx[8];
        if (threadIdx.x < 8) idx[threadIdx.x] = nodes[(m + 1) * 8 + threadIdx.x];
        __syncthreads();
        int c = threadIdx.x;                     // float4 column 0..79 (75..79 = pad)
        if (c < K0PAD / 4) {
            __half2 h0 = __float2half2_rn(0.f), h1 = h0;
            if (c < EMBED / 4) {
                float4 mx = *(const float4*)(emb + (size_t)idx[0] * EMBED + c * 4);
                #pragma unroll
                for (int r = 1; r < 8; ++r) {
                    float4 v = *(const float4*)(emb + (size_t)idx[r] * EMBED + c * 4);
                    mx.x = fmaxf(mx.x, v.x); mx.y = fmaxf(mx.y, v.y);
                    mx.z = fmaxf(mx.z, v.z); mx.w = fmaxf(mx.w, v.w);
                }
                h0 = __floats2half2_rn(mx.x, mx.y);
                h1 = __floats2half2_rn(mx.z, mx.w);
            }
            uint2 pk = make_uint2(*(uint32_t*)&h0, *(uint32_t*)&h1);
            *(uint2*)(g_xh + (size_t)m * K0PAD + c * 4) = pk;
        }
    } else if (b < GB_W1) {
        int i = (b - GB_GATHER) * 128 + threadIdx.x;
        int n = i / K0PAD, k = i % K0PAD;
        g_w1t[i] = (k < EMBED) ? __float2half_rn(W1[(size_t)k * HID + n]) : __half(0);
    } else {
        int i = (b - GB_W1) * 128 + threadIdx.x;
        int n = i / HID, k = i % HID;
        g_w2t[i] = __float2half_rn(W2[(size_t)k * HID + n]);
    }
}

// ---------------------------------------------------------------------------
// Kernel 3: small GEMM via mma (layer 0 only):  g_yTh = (x@W1)^T
// ---------------------------------------------------------------------------
__global__ void __launch_bounds__(256, 1)
small_mma_kernel() {
    extern __shared__ char smem[];
    uint32_t sb = smem_u32(smem);
    const __half* A  = g_xh;
    const __half* Wt = g_w1t;
    const int ldk     = K0PAD;
    const int kchunks = K0PAD / BK;
    int tid = threadIdx.x;
    int w = tid >> 5, lane = tid & 31;
    int m0 = blockIdx.x * SBM;

    float acc[8][4][4];
    #pragma unroll
    for (int a = 0; a < 8; ++a)
        #pragma unroll
        for (int b = 0; b < 4; ++b)
            #pragma unroll
            for (int c = 0; c < 4; ++c) acc[a][b][c] = 0.f;

    auto fill = [&](int chunk) {
        int s = chunk & (SSTAGES - 1);
        int k0 = chunk * BK;
        uint32_t sa = sb + SSM_A(s), sB = sb + SSM_B(s);
        #pragma unroll
        for (int i = 0; i < 4; ++i) {
            int c = tid + i * 256;
            int row = c >> 3, ch = c & 7;
            int gm = m0 + row;
            int ok = gm < N_NODES;
            const __half* g = A + (size_t)(ok ? gm : 0) * ldk + k0 + ch * 8;
            cp_async16(sa + SWZ(row * 128 + ch * 16), g, ok ? 16u : 0u);
        }
        #pragma unroll
        for (int i = 0; i < 8; ++i) {
            int c = tid + i * 256;
            int row = c >> 3, ch = c & 7;
            cp_async16(sB + SWZ(row * 128 + ch * 16),
                       Wt + (size_t)row * ldk + k0 + ch * 8, 16u);
        }
        CP_COMMIT();
    };

    fill(0); fill(1); fill(2);

    for (int j = 0; j < kchunks; ++j) {
        asm volatile("cp.async.wait_group %0;" :: "n"(SSTAGES - 2));
        __syncthreads();
        if (j + 3 < kchunks) fill(j + 3); else CP_COMMIT();

        int s = j & (SSTAGES - 1);
        uint32_t sa = sb + SSM_A(s), sB = sb + SSM_B(s);
        #pragma unroll
        for (int ks = 0; ks < 4; ++ks) {
            uint32_t bf[4], bf2[4];
            {
                uint32_t row = w * 32 + ((lane >> 4) & 1) * 8 + (lane & 7);
                uint32_t off = row * 128 + ks * 32 + ((lane >> 3) & 1) * 16;
                ldsm_x4(bf, sB + SWZ(off));
                uint32_t row2 = w * 32 + 16 + ((lane >> 4) & 1) * 8 + (lane & 7);
                uint32_t off2 = row2 * 128 + ks * 32 + ((lane >> 3) & 1) * 16;
                ldsm_x4(bf2, sB + SWZ(off2));
            }
            #pragma unroll
            for (int mt = 0; mt < 8; ++mt) {
                uint32_t af[4];
                uint32_t off = (uint32_t)(mt * 16 + (lane & 15)) * 128 + ks * 32 + (lane >> 4) * 16;
                ldsm_x4(af, sa + SWZ(off));
                mma16816(acc[mt][0], af, bf[0],  bf[1]);
                mma16816(acc[mt][1], af, bf[2],  bf[3]);
                mma16816(acc[mt][2], af, bf2[0], bf2[1]);
                mma16816(acc[mt][3], af, bf2[2], bf2[3]);
            }
        }
    }

    __syncthreads();
    __half* st = (__half*)(smem) + (size_t)w * 32 * 136;
    int qr = lane >> 2, qc = lane & 3;
    #pragma unroll
    for (int mt = 0; mt < 8; ++mt) {
        int ml = mt * 16 + qr;
        #pragma unroll
        for (int nt = 0; nt < 4; ++nt) {
            int nl = nt * 8 + qc * 2;
            st[(size_t)nl * 136 + ml]           = __float2half_rn(acc[mt][nt][0]);
            st[(size_t)(nl + 1) * 136 + ml]     = __float2half_rn(acc[mt][nt][1]);
            st[(size_t)nl * 136 + ml + 8]       = __float2half_rn(acc[mt][nt][2]);
            st[(size_t)(nl + 1) * 136 + ml + 8] = __float2half_rn(acc[mt][nt][3]);
        }
    }
    __syncwarp();
    #pragma unroll 4
    for (int nl = 0; nl < 32; ++nl) {
        int m = m0 + lane * 4;
        if (m < N_NODES)
            *(uint2*)&g_yTh[(size_t)(w * 32 + nl) * N_NODES + m] =
                *(uint2*)&st[(size_t)nl * 136 + lane * 4];
    }
}

// ---------------------------------------------------------------------------
// Kernel 4: big GEMM (R13 champion, verbatim). Layer 1 (adjf != null): fused
// fp32->fp16 adj conversion + fused y2 = h1 @ W2 -> g_yTh.
// Layer 2 (dout != null): plain epilogue -> fp32 out.
// ---------------------------------------------------------------------------
__global__ void __launch_bounds__(256, 1)
big_gemm_kernel(const float* __restrict__ adjf, const float* __restrict__ bias,
                float* __restrict__ dout) {
    extern __shared__ char smem[];
    uint32_t sb = smem_u32(smem);
    int tid = threadIdx.x;
    int w = tid >> 5, lane = tid & 31;
    int m0 = blockIdx.x * BM;

    ((float*)(smem + SM_BIAS))[tid] = bias[tid];

    float acc[5][4][4];
    #pragma unroll
    for (int a = 0; a < 5; ++a)
        #pragma unroll
        for (int b = 0; b < 4; ++b)
            #pragma unroll
            for (int c = 0; c < 4; ++c) acc[a][b][c] = 0.f;

    float4 areg[5];
    int arow[5], acol[5];
    #pragma unroll
    for (int i = 0; i < 5; ++i) {
        int c = tid + i * 256;
        arow[i] = c >> 4;
        acol[i] = (c & 15) * 4;
    }

    auto ldgA = [&](int chunk) {
        int k0 = chunk * BK;
        #pragma unroll
        for (int i = 0; i < 5; ++i) {
            int kk = k0 + acol[i];
            if (kk < N_NODES)
                areg[i] = *(const float4*)(adjf + (size_t)(m0 + arow[i]) * N_NODES + kk);
            else
                areg[i] = make_float4(0.f, 0.f, 0.f, 0.f);
        }
    };
    auto stsA = [&](int chunk) {
        int s = chunk % STAGES;
        int k0 = chunk * BK;
        #pragma unroll
        for (int i = 0; i < 5; ++i) {
            __half2 h0 = __floats2half2_rn(areg[i].x * ADJ_SCALE, areg[i].y * ADJ_SCALE);
            __half2 h1 = __floats2half2_rn(areg[i].z * ADJ_SCALE, areg[i].w * ADJ_SCALE);
            uint2 pk = make_uint2(*(uint32_t*)&h0, *(uint32_t*)&h1);
            *(uint2*)(smem + (SWZ((uint32_t)arow[i] * 128 + acol[i] * 2) + SM_A(s))) = pk;
            int kk = k0 + acol[i];
            if (kk < N_NODES)
                *(uint2*)&g_adjh[(size_t)(m0 + arow[i]) * N_NODES + kk] = pk;
        }
    };
    auto fillA_async = [&](int chunk) {
        int s = chunk % STAGES;
        int k0 = chunk * BK;
        uint32_t sa = sb + SM_A(s);
        #pragma unroll
        for (int i = 0; i < 3; ++i) {
            int c = tid + i * 256;
            if (c < 640) {
                int row = c >> 3, ch = c & 7;
                int kk = k0 + ch * 8;
                int ok = kk < N_NODES;
                const __half* g = g_adjh + (size_t)(m0 + row) * N_NODES + (ok ? kk : 0);
                cp_async16(sa + SWZ(row * 128 + ch * 16), g, ok ? 16u : 0u);
            }
        }
    };
    auto fillB = [&](int chunk) {
        int s = chunk % STAGES;
        int k0 = chunk * BK;
        uint32_t sB = sb + SM_B(s);
        #pragma unroll
        for (int i = 0; i < 8; ++i) {
            int c = tid + i * 256;
            int row = c >> 3, ch = c & 7;
            int kk = k0 + ch * 8;
            int ok = kk < N_NODES;
            const __half* g = g_yTh + (size_t)row * N_NODES + (ok ? kk : 0);
            cp_async16(sB + SWZ(row * 128 + ch * 16), g, ok ? 16u : 0u);
        }
    };
    auto consume = [&](int j) {
        int s = j % STAGES;
        uint32_t sa = sb + SM_A(s), sB = sb + SM_B(s);
        #pragma unroll
        for (int ks = 0; ks < 4; ++ks) {
            uint32_t af[5][4];
            #pragma unroll
            for (int mt = 0; mt < 5; ++mt) {
                uint32_t off = (uint32_t)(mt * 16 + (lane & 15)) * 128 + ks * 32 + (lane >> 4) * 16;
                ldsm_x4(af[mt], sa + SWZ(off));
            }
            uint32_t bf[4], bf2[4];
            {
                uint32_t row = w * 32 + ((lane >> 4) & 1) * 8 + (lane & 7);
                uint32_t off = row * 128 + ks * 32 + ((lane >> 3) & 1) * 16;
                ldsm_x4(bf, sB + SWZ(off));
                uint32_t row2 = w * 32 + 16 + ((lane >> 4) & 1) * 8 + (lane & 7);
                uint32_t off2 = row2 * 128 + ks * 32 + ((lane >> 3) & 1) * 16;
                ldsm_x4(bf2, sB + SWZ(off2));
            }
            #pragma unroll
            for (int mt = 0; mt < 5; ++mt) {
                mma16816(acc[mt][0], af[mt], bf[0],  bf[1]);
                mma16816(acc[mt][1], af[mt], bf[2],  bf[3]);
                mma16816(acc[mt][2], af[mt], bf2[0], bf2[1]);
                mma16816(acc[mt][3], af[mt], bf2[2], bf2[3]);
            }
        }
    };

    if (adjf) {
        ldgA(0); stsA(0); ldgA(1); stsA(1); ldgA(2); stsA(2); ldgA(3);
        fillB(0); CP_COMMIT(); fillB(1); CP_COMMIT(); fillB(2); CP_COMMIT();
    } else {
        fillA_async(0); fillB(0); CP_COMMIT();
        fillA_async(1); fillB(1); CP_COMMIT();
        fillA_async(2); fillB(2); CP_COMMIT();
    }

    int j = 0;
    for (; j + 2 < NKCH; j += 2) {
        asm volatile("cp.async.wait_group %0;" :: "n"(1));
        __syncthreads();
        if (adjf) {
            if (j + 3 < NKCH) { fillB(j + 3); stsA(j + 3); }
            CP_COMMIT();
            if (j + 4 < NKCH) { fillB(j + 4); ldgA(j + 4); }
            CP_COMMIT();
            consume(j);
            if (j + 4 < NKCH) stsA(j + 4);
            if (j + 5 < NKCH) ldgA(j + 5);
            consume(j + 1);
        } else {
            if (j + 3 < NKCH) { fillA_async(j + 3); fillB(j + 3); }
            CP_COMMIT();
            if (j + 4 < NKCH) { fillA_async(j + 4); fillB(j + 4); }
            CP_COMMIT();
            consume(j);
            consume(j + 1);
        }
    }
    asm volatile("cp.async.wait_group %0;" :: "n"(0));
    __syncthreads();
    consume(NKCH - 1);

    const float* bsm = (const float*)(smem + SM_BIAS);
    int qr = lane >> 2, qc = lane & 3;

    if (dout) {
        #pragma unroll
        for (int mt = 0; mt < 5; ++mt) {
            int r0 = m0 + mt * 16 + qr;
            #pragma unroll
            for (int nt = 0; nt < 4; ++nt) {
                int col = w * 32 + nt * 8 + qc * 2;
                float b0 = bsm[col], b1 = bsm[col + 1];
                float v0 = acc[mt][nt][0] * ADJ_INV + b0;
                float v1 = acc[mt][nt][1] * ADJ_INV + b1;
                float v2 = acc[mt][nt][2] * ADJ_INV + b0;
                float v3 = acc[mt][nt][3] * ADJ_INV + b1;
                v0 = fmaxf(v0, 0.01f * v0); v1 = fmaxf(v1, 0.01f * v1);
                v2 = fmaxf(v2, 0.01f * v2); v3 = fmaxf(v3, 0.01f * v3);
                *(float2*)&dout[(size_t)r0 * HID + col]       = make_float2(v0, v1);
                *(float2*)&dout[(size_t)(r0 + 8) * HID + col] = make_float2(v2, v3);
            }
        }
        return;
    }

    // ---- layer-1 fused epilogue: h1 -> smem fp16, then y2 = h1 @ W2 -> g_yTh ----
    #pragma unroll
    for (int mt = 0; mt < 5; ++mt) {
        int lr = mt * 16 + qr;
        #pragma unroll
        for (int nt = 0; nt < 4; ++nt) {
            int col = w * 32 + nt * 8 + qc * 2;
            float b0 = bsm[col], b1 = bsm[col + 1];
            float v0 = acc[mt][nt][0] * ADJ_INV + b0;
            float v1 = acc[mt][nt][1] * ADJ_INV + b1;
            float v2 = acc[mt][nt][2] * ADJ_INV + b0;
            float v3 = acc[mt][nt][3] * ADJ_INV + b1;
            v0 = fmaxf(v0, 0.01f * v0); v1 = fmaxf(v1, 0.01f * v1);
            v2 = fmaxf(v2, 0.01f * v2); v3 = fmaxf(v3, 0.01f * v3);
            int kc = col >> 6, cc = col & 63;
            uint32_t base = H1_OFF + kc * H1_CHUNK;
            *(__half2*)(smem + base + SWZ((uint32_t)lr * 128 + cc * 2))       = __floats2half2_rn(v0, v1);
            *(__half2*)(smem + base + SWZ((uint32_t)(lr + 8) * 128 + cc * 2)) = __floats2half2_rn(v2, v3);
        }
    }
    __syncthreads();

    auto fillW2 = [&](int kc) {
        uint32_t dst = sb + W2B_OFF + (kc & 1) * W2B_BYTES;
        #pragma unroll
        for (int i = 0; i < 8; ++i) {
            int c = tid + i * 256;
            int row = c >> 3, ch = c & 7;
            cp_async16(dst + SWZ(row * 128 + ch * 16),
                       g_w2t + (size_t)row * HID + kc * 64 + ch * 8, 16u);
        }
        CP_COMMIT();
    };
    fillW2(0); fillW2(1);

    #pragma unroll
    for (int a = 0; a < 5; ++a)
        #pragma unroll
        for (int b = 0; b < 4; ++b)
            #pragma unroll
            for (int c = 0; c < 4; ++c) acc[a][b][c] = 0.f;

    for (int kc = 0; kc < 4; ++kc) {
        if (kc < 3) { asm volatile("cp.async.wait_group %0;" :: "n"(1)); }
        else        { asm volatile("cp.async.wait_group %0;" :: "n"(0)); }
        __syncthreads();
        uint32_t sa = sb + H1_OFF + kc * H1_CHUNK;
        uint32_t sB = sb + W2B_OFF + (kc & 1) * W2B_BYTES;
        #pragma unroll
        for (int ks = 0; ks < 4; ++ks) {
            uint32_t af[5][4];
            #pragma unroll
            for (int mt = 0; mt < 5; ++mt) {
                uint32_t off = (uint32_t)(mt * 16 + (lane & 15)) * 128 + ks * 32 + (lane >> 4) * 16;
                ldsm_x4(af[mt], sa + SWZ(off));
            }
            uint32_t bf[4], bf2[4];
            {
                uint32_t row = w * 32 + ((lane >> 4) & 1) * 8 + (lane & 7);
                uint32_t off = row * 128 + ks * 32 + ((lane >> 3) & 1) * 16;
                ldsm_x4(bf, sB + SWZ(off));
                uint32_t row2 = w * 32 + 16 + ((lane >> 4) & 1) * 8 + (lane & 7);
                uint32_t off2 = row2 * 128 + ks * 32 + ((lane >> 3) & 1) * 16;
                ldsm_x4(bf2, sB + SWZ(off2));
            }
            #pragma unroll
            for (int mt = 0; mt < 5; ++mt) {
                mma16816(acc[mt][0], af[mt], bf[0],  bf[1]);
                mma16816(acc[mt][1], af[mt], bf[2],  bf[3]);
                mma16816(acc[mt][2], af[mt], bf2[0], bf2[1]);
                mma16816(acc[mt][3], af[mt], bf2[2], bf2[3]);
            }
        }
        __syncthreads();
        if (kc + 2 < 4) fillW2(kc + 2);
    }

    __half* st = (__half*)(smem + Y2ST_OFF) + (size_t)w * 32 * 88;
    #pragma unroll
    for (int mt = 0; mt < 5; ++mt) {
        int lr = mt * 16 + qr;
        #pragma unroll
        for (int nt = 0; nt < 4; ++nt) {
            int nl = nt * 8 + qc * 2;
            st[nl * 88 + lr]           = __float2half_rn(acc[mt][nt][0]);
            st[(nl + 1) * 88 + lr]     = __float2half_rn(acc[mt][nt][1]);
            st[nl * 88 + lr + 8]       = __float2half_rn(acc[mt][nt][2]);
            st[(nl + 1) * 88 + lr + 8] = __float2half_rn(acc[mt][nt][3]);
        }
    }
    __syncwarp();
    if (lane < 20) {
        #pragma unroll 4
        for (int nl = 0; nl < 32; ++nl) {
            *(uint2*)&g_yTh[(size_t)(w * 32 + nl) * N_NODES + m0 + lane * 4] =
                *(uint2*)&st[nl * 88 + lane * 4];
        }
    }
}

// ---------------------------------------------------------------------------
extern "C" void kernel_launch(void* const* d_in, const int* in_sizes, int n_in,
                              void* d_out, int out_size) {
    (void)in_sizes; (void)n_in; (void)out_size;
    const int*   nodes = (const int*)  d_in[0];
    const float* emb   = (const float*)d_in[1];
    const float* adj   = (const float*)d_in[2];
    const float* W1    = (const float*)d_in[3];
    const float* b1    = (const float*)d_in[4];
    const float* W2    = (const float*)d_in[5];
    const float* b2    = (const float*)d_in[6];
    float* out = (float*)d_out;

    cudaFuncSetAttribute(big_gemm_kernel, cudaFuncAttributeMaxDynamicSharedMemorySize, SMEM_BYTES);
    cudaFuncSetAttribute(small_mma_kernel, cudaFuncAttributeMaxDynamicSharedMemorySize, SSMEM_BYTES);

    int gm = N_NODES / BM;                     // 125, 1 CTA/SM
    int gsm = (N_NODES + SBM - 1) / SBM;       // 79

    prep_kernel<<<GB_END, 128>>>(nodes, emb, W1, W2);             // gather + W1^T + W2^T
    small_mma_kernel<<<gsm, 256, SSMEM_BYTES>>>();                // g_yTh = (x@W1)^T
    big_gemm_kernel<<<gm, 256, SMEM_BYTES>>>(adj, b1, nullptr);   // convert + h1 + y2 -> g_yTh
    big_gemm_kernel<<<gm, 256, SMEM_BYTES>>>(nullptr, b2, out);   // out = lrelu(adj@y2 + b2)
}

// round 16
// speedup vs baseline: 1.0469x; 1.0064x over previous
#include <cuda_runtime.h>
#include <cuda_fp16.h>
#include <cstdint>
#include <cstddef>

#define N_NODES 10000
#define EMBED   300
#define K0PAD   320
#define HID     256

// ---- big GEMM tiling: BM=80 x BN=256, 125 CTAs, 1 CTA/SM, 5-stage ring ----
#define BM      80
#define BK      64
#define NKCH    157
#define STAGES  5

#define ADJ_SCALE  16384.0f
#define ADJ_INV    6.103515625e-05f

#define SM_BIAS   0
#define A_BYTES   (BM  * BK * 2)
#define B_BYTES   (256 * BK * 2)
#define STG_BYTES (A_BYTES + B_BYTES)           // 43008
#define SM_A(s)   (1024 + (s) * STG_BYTES)
#define SM_B(s)   (SM_A(s) + A_BYTES)
#define SMEM_BYTES (1024 + STAGES * STG_BYTES)  // 216064 -> 1 CTA/SM

// ---- fused layer-1 epilogue (y2 = h1 @ W2): 3-buffer W2 ring ----
#define H1_OFF    1024
#define H1_CHUNK  (BM * 128)                    // 10240
#define W2B_OFF   (H1_OFF + 4 * H1_CHUNK)       // 41984
#define W2B_BYTES (256 * 128)                   // 32768
#define Y2ST_OFF  (W2B_OFF + 3 * W2B_BYTES)     // 140288; +45056 = 185344 < 216064

// ---- small GEMM tiling: 80m x 256n, 125 CTAs (one wave), 4 stages ----
#define SBM       80
#define SA_BYTES  (SBM * BK * 2)                // 10240
#define SB_BYTES  (256 * BK * 2)                // 32768
#define SSTG      (SA_BYTES + SB_BYTES)         // 43008
#define SSM_A(s)  ((s) * SSTG)
#define SSM_B(s)  (SSM_A(s) + SA_BYTES)
#define SSMEM_BYTES (4 * SSTG)                  // 172032

// ---- device scratch (only ever referenced from DEVICE code) ----
__device__ __align__(1024) __half g_adjh[(size_t)N_NODES * N_NODES];
__device__ __align__(1024) __half g_xh  [N_NODES * K0PAD];
__device__ __align__(1024) __half g_yTh [HID * N_NODES];
__device__ __align__(1024) __half g_w1t [HID * K0PAD];
__device__ __align__(1024) __half g_w2t [HID * HID];

// ---------------------------------------------------------------------------
static __device__ __forceinline__ uint32_t smem_u32(const void* p) {
    uint32_t a;
    asm("{ .reg .u64 t; cvta.to.shared.u64 t, %1; cvt.u32.u64 %0, t; }" : "=r"(a) : "l"(p));
    return a;
}
#define SWZ(b) ((b) ^ (((b) >> 3) & 0x70))

static __device__ __forceinline__ void cp_async16(uint32_t dst, const void* src, uint32_t nbytes) {
    asm volatile("cp.async.cg.shared.global [%0], [%1], 16, %2;"
        :: "r"(dst), "l"(src), "r"(nbytes) : "memory");
}
#define CP_COMMIT() asm volatile("cp.async.commit_group;" ::: "memory")

static __device__ __forceinline__ void ldsm_x4(uint32_t r[4], uint32_t addr) {
    asm volatile("ldmatrix.sync.aligned.m8n8.x4.shared.b16 {%0,%1,%2,%3}, [%4];"
        : "=r"(r[0]), "=r"(r[1]), "=r"(r[2]), "=r"(r[3]) : "r"(addr));
}
static __device__ __forceinline__ void mma16816(float c[4], const uint32_t a[4],
                                                uint32_t b0, uint32_t b1) {
    asm volatile("mma.sync.aligned.m16n8k16.row.col.f32.f16.f16.f32 "
        "{%0,%1,%2,%3}, {%4,%5,%6,%7}, {%8,%9}, {%0,%1,%2,%3};"
        : "+f"(c[0]), "+f"(c[1]), "+f"(c[2]), "+f"(c[3])
        : "r"(a[0]), "r"(a[1]), "r"(a[2]), "r"(a[3]), "r"(b0), "r"(b1));
}

// ---------------------------------------------------------------------------
// Kernel 1 (fused prep): blocks [0,10000): gather+max -> g_xh (float4 loads)
//                        blocks [10000,10640): W1^T; [10640,11152): W2^T
// ---------------------------------------------------------------------------
#define GB_GATHER 10000
#define GB_W1     (GB_GATHER + (256 * K0PAD) / 128)   // 10000 + 640
#define GB_END    (GB_W1 + (256 * HID) / 128)         // + 512

__global__ void prep_kernel(const int* __restrict__ nodes, const float* __restrict__ emb,
                            const float* __restrict__ W1, const float* __restrict__ W2) {
    int b = blockIdx.x;
    if (b < GB_GATHER) {
        int m = b;
        __shared__ int idx[8];
        if (threadIdx.x < 8) idx[threadIdx.x] = nodes[(m + 1) * 8 + threadIdx.x];
        __syncthreads();
        int c = threadIdx.x;                     // float4 column 0..79 (75..79 = pad)
        if (c < K0PAD / 4) {
            __half2 h0 = __float2half2_rn(0.f), h1 = h0;
            if (c < EMBED / 4) {
                float4 mx = *(const float4*)(emb + (size_t)idx[0] * EMBED + c * 4);
                #pragma unroll
                for (int r = 1; r < 8; ++r) {
                    float4 v = *(const float4*)(emb + (size_t)idx[r] * EMBED + c * 4);
                    mx.x = fmaxf(mx.x, v.x); mx.y = fmaxf(mx.y, v.y);
                    mx.z = fmaxf(mx.z, v.z); mx.w = fmaxf(mx.w, v.w);
                }
                h0 = __floats2half2_rn(mx.x, mx.y);
                h1 = __floats2half2_rn(mx.z, mx.w);
            }
            uint2 pk = make_uint2(*(uint32_t*)&h0, *(uint32_t*)&h1);
            *(uint2*)(g_xh + (size_t)m * K0PAD + c * 4) = pk;
        }
    } else if (b < GB_W1) {
        int i = (b - GB_GATHER) * 128 + threadIdx.x;
        int n = i / K0PAD, k = i % K0PAD;
        g_w1t[i] = (k < EMBED) ? __float2half_rn(W1[(size_t)k * HID + n]) : __half(0);
    } else {
        int i = (b - GB_W1) * 128 + threadIdx.x;
        int n = i / HID, k = i % HID;
        g_w2t[i] = __float2half_rn(W2[(size_t)k * HID + n]);
    }
}

// ---------------------------------------------------------------------------
// Kernel 3: small GEMM via mma:  g_yTh = (x@W1)^T
// SBM=80 x 256n, 125 CTAs (one full wave), warp tile 80x32 (mt=5), 4-stage.
// ---------------------------------------------------------------------------
__global__ void __launch_bounds__(256, 1)
small_mma_kernel() {
    extern __shared__ char smem[];
    uint32_t sb = smem_u32(smem);
    int tid = threadIdx.x;
    int w = tid >> 5, lane = tid & 31;
    int m0 = blockIdx.x * SBM;   // 125*80 = 10000 exact, no m-guards needed

    float acc[5][4][4];
    #pragma unroll
    for (int a = 0; a < 5; ++a)
        #pragma unroll
        for (int b = 0; b < 4; ++b)
            #pragma unroll
            for (int c = 0; c < 4; ++c) acc[a][b][c] = 0.f;

    auto fill = [&](int chunk) {
        int s = chunk & 3;
        int k0 = chunk * BK;                    // <= 256; K0PAD=320, always in-bounds
        uint32_t sa = sb + SSM_A(s), sB = sb + SSM_B(s);
        #pragma unroll
        for (int i = 0; i < 3; ++i) {           // A: 640 16B units
            int c = tid + i * 256;
            if (c < 640) {
                int row = c >> 3, ch = c & 7;
                cp_async16(sa + SWZ(row * 128 + ch * 16),
                           g_xh + (size_t)(m0 + row) * K0PAD + k0 + ch * 8, 16u);
            }
        }
        #pragma unroll
        for (int i = 0; i < 8; ++i) {           // B: 2048 16B units
            int c = tid + i * 256;
            int row = c >> 3, ch = c & 7;
            cp_async16(sB + SWZ(row * 128 + ch * 16),
                       g_w1t + (size_t)row * K0PAD + k0 + ch * 8, 16u);
        }
        CP_COMMIT();
    };

    fill(0); fill(1); fill(2);

    for (int j = 0; j < K0PAD / BK; ++j) {      // 5 chunks
        asm volatile("cp.async.wait_group %0;" :: "n"(2));
        __syncthreads();
        if (j + 3 < K0PAD / BK) fill(j + 3); else CP_COMMIT();

        int s = j & 3;
        uint32_t sa = sb + SSM_A(s), sB = sb + SSM_B(s);
        #pragma unroll
        for (int ks = 0; ks < 4; ++ks) {
            uint32_t bf[4], bf2[4];
            {
                uint32_t row = w * 32 + ((lane >> 4) & 1) * 8 + (lane & 7);
                uint32_t off = row * 128 + ks * 32 + ((lane >> 3) & 1) * 16;
                ldsm_x4(bf, sB + SWZ(off));
                uint32_t row2 = w * 32 + 16 + ((lane >> 4) & 1) * 8 + (lane & 7);
                uint32_t off2 = row2 * 128 + ks * 32 + ((lane >> 3) & 1) * 16;
                ldsm_x4(bf2, sB + SWZ(off2));
            }
            #pragma unroll
            for (int mt = 0; mt < 5; ++mt) {
                uint32_t af[4];
                uint32_t off = (uint32_t)(mt * 16 + (lane & 15)) * 128 + ks * 32 + (lane >> 4) * 16;
                ldsm_x4(af, sa + SWZ(off));
                mma16816(acc[mt][0], af, bf[0],  bf[1]);
                mma16816(acc[mt][1], af, bf[2],  bf[3]);
                mma16816(acc[mt][2], af, bf2[0], bf2[1]);
                mma16816(acc[mt][3], af, bf2[2], bf2[3]);
            }
        }
    }

    // transposed epilogue (stride 88, 80 rows per warp tile)
    __syncthreads();
    __half* st = (__half*)(smem) + (size_t)w * 32 * 88;
    int qr = lane >> 2, qc = lane & 3;
    #pragma unroll
    for (int mt = 0; mt < 5; ++mt) {
        int ml = mt * 16 + qr;
        #pragma unroll
        for (int nt = 0; nt < 4; ++nt) {
            int nl = nt * 8 + qc * 2;
            st[nl * 88 + ml]           = __float2half_rn(acc[mt][nt][0]);
            st[(nl + 1) * 88 + ml]     = __float2half_rn(acc[mt][nt][1]);
            st[nl * 88 + ml + 8]       = __float2half_rn(acc[mt][nt][2]);
            st[(nl + 1) * 88 + ml + 8] = __float2half_rn(acc[mt][nt][3]);
        }
    }
    __syncwarp();
    if (lane < 20) {
        #pragma unroll 4
        for (int nl = 0; nl < 32; ++nl)
            *(uint2*)&g_yTh[(size_t)(w * 32 + nl) * N_NODES + m0 + lane * 4] =
                *(uint2*)&st[nl * 88 + lane * 4];
    }
}

// ---------------------------------------------------------------------------
// Kernel 4: big GEMM. Layer 1 (adjf != null): fused fp32->fp16 adj conversion
// + fused y2 = h1 @ W2 -> g_yTh (3-buffer W2 ring, 1 sync/chunk).
// Layer 2 (dout != null): plain epilogue -> fp32 out.
// ---------------------------------------------------------------------------
__global__ void __launch_bounds__(256, 1)
big_gemm_kernel(const float* __restrict__ adjf, const float* __restrict__ bias,
                float* __restrict__ dout) {
    extern __shared__ char smem[];
    uint32_t sb = smem_u32(smem);
    int tid = threadIdx.x;
    int w = tid >> 5, lane = tid & 31;
    int m0 = blockIdx.x * BM;

    ((float*)(smem + SM_BIAS))[tid] = bias[tid];

    float acc[5][4][4];
    #pragma unroll
    for (int a = 0; a < 5; ++a)
        #pragma unroll
        for (int b = 0; b < 4; ++b)
            #pragma unroll
            for (int c = 0; c < 4; ++c) acc[a][b][c] = 0.f;

    float4 areg[5];
    int arow[5], acol[5];
    #pragma unroll
    for (int i = 0; i < 5; ++i) {
        int c = tid + i * 256;
        arow[i] = c >> 4;
        acol[i] = (c & 15) * 4;
    }

    auto ldgA = [&](int chunk) {
        int k0 = chunk * BK;
        #pragma unroll
        for (int i = 0; i < 5; ++i) {
            int kk = k0 + acol[i];
            if (kk < N_NODES)
                areg[i] = *(const float4*)(adjf + (size_t)(m0 + arow[i]) * N_NODES + kk);
            else
                areg[i] = make_float4(0.f, 0.f, 0.f, 0.f);
        }
    };
    auto stsA = [&](int chunk) {
        int s = chunk % STAGES;
        int k0 = chunk * BK;
        #pragma unroll
        for (int i = 0; i < 5; ++i) {
            __half2 h0 = __floats2half2_rn(areg[i].x * ADJ_SCALE, areg[i].y * ADJ_SCALE);
            __half2 h1 = __floats2half2_rn(areg[i].z * ADJ_SCALE, areg[i].w * ADJ_SCALE);
            uint2 pk = make_uint2(*(uint32_t*)&h0, *(uint32_t*)&h1);
            *(uint2*)(smem + (SWZ((uint32_t)arow[i] * 128 + acol[i] * 2) + SM_A(s))) = pk;
            int kk = k0 + acol[i];
            if (kk < N_NODES)
                *(uint2*)&g_adjh[(size_t)(m0 + arow[i]) * N_NODES + kk] = pk;
        }
    };
    auto fillA_async = [&](int chunk) {
        int s = chunk % STAGES;
        int k0 = chunk * BK;
        uint32_t sa = sb + SM_A(s);
        #pragma unroll
        for (int i = 0; i < 3; ++i) {
            int c = tid + i * 256;
            if (c < 640) {
                int row = c >> 3, ch = c & 7;
                int kk = k0 + ch * 8;
                int ok = kk < N_NODES;
                const __half* g = g_adjh + (size_t)(m0 + row) * N_NODES + (ok ? kk : 0);
                cp_async16(sa + SWZ(row * 128 + ch * 16), g, ok ? 16u : 0u);
            }
        }
    };
    auto fillB = [&](int chunk) {
        int s = chunk % STAGES;
        int k0 = chunk * BK;
        uint32_t sB = sb + SM_B(s);
        #pragma unroll
        for (int i = 0; i < 8; ++i) {
            int c = tid + i * 256;
            int row = c >> 3, ch = c & 7;
            int kk = k0 + ch * 8;
            int ok = kk < N_NODES;
            const __half* g = g_yTh + (size_t)row * N_NODES + (ok ? kk : 0);
            cp_async16(sB + SWZ(row * 128 + ch * 16), g, ok ? 16u : 0u);
        }
    };
    auto consume = [&](int j) {
        int s = j % STAGES;
        uint32_t sa = sb + SM_A(s), sB = sb + SM_B(s);
        #pragma unroll
        for (int ks = 0; ks < 4; ++ks) {
            uint32_t af[5][4];
            #pragma unroll
            for (int mt = 0; mt < 5; ++mt) {
                uint32_t off = (uint32_t)(mt * 16 + (lane & 15)) * 128 + ks * 32 + (lane >> 4) * 16;
                ldsm_x4(af[mt], sa + SWZ(off));
            }
            uint32_t bf[4], bf2[4];
            {
                uint32_t row = w * 32 + ((lane >> 4) & 1) * 8 + (lane & 7);
                uint32_t off = row * 128 + ks * 32 + ((lane >> 3) & 1) * 16;
                ldsm_x4(bf, sB + SWZ(off));
                uint32_t row2 = w * 32 + 16 + ((lane >> 4) & 1) * 8 + (lane & 7);
                uint32_t off2 = row2 * 128 + ks * 32 + ((lane >> 3) & 1) * 16;
                ldsm_x4(bf2, sB + SWZ(off2));
            }
            #pragma unroll
            for (int mt = 0; mt < 5; ++mt) {
                mma16816(acc[mt][0], af[mt], bf[0],  bf[1]);
                mma16816(acc[mt][1], af[mt], bf[2],  bf[3]);
                mma16816(acc[mt][2], af[mt], bf2[0], bf2[1]);
                mma16816(acc[mt][3], af[mt], bf2[2], bf2[3]);
            }
        }
    };

    if (adjf) {
        ldgA(0); stsA(0); ldgA(1); stsA(1); ldgA(2); stsA(2); ldgA(3);
        fillB(0); CP_COMMIT(); fillB(1); CP_COMMIT(); fillB(2); CP_COMMIT();
    } else {
        fillA_async(0); fillB(0); CP_COMMIT();
        fillA_async(1); fillB(1); CP_COMMIT();
        fillA_async(2); fillB(2); CP_COMMIT();
    }

    int j = 0;
    for (; j + 2 < NKCH; j += 2) {
        asm volatile("cp.async.wait_group %0;" :: "n"(1));
        __syncthreads();
        if (adjf) {
            if (j + 3 < NKCH) { fillB(j + 3); stsA(j + 3); }
            CP_COMMIT();
            if (j + 4 < NKCH) { fillB(j + 4); ldgA(j + 4); }
            CP_COMMIT();
            consume(j);
            if (j + 4 < NKCH) stsA(j + 4);
            if (j + 5 < NKCH) ldgA(j + 5);
            consume(j + 1);
        } else {
            if (j + 3 < NKCH) { fillA_async(j + 3); fillB(j + 3); }
            CP_COMMIT();
            if (j + 4 < NKCH) { fillA_async(j + 4); fillB(j + 4); }
            CP_COMMIT();
            consume(j);
            consume(j + 1);
        }
    }
    asm volatile("cp.async.wait_group %0;" :: "n"(0));
    __syncthreads();
    consume(NKCH - 1);

    const float* bsm = (const float*)(smem + SM_BIAS);
    int qr = lane >> 2, qc = lane & 3;

    if (dout) {
        #pragma unroll
        for (int mt = 0; mt < 5; ++mt) {
            int r0 = m0 + mt * 16 + qr;
            #pragma unroll
            for (int nt = 0; nt < 4; ++nt) {
                int col = w * 32 + nt * 8 + qc * 2;
                float b0 = bsm[col], b1 = bsm[col + 1];
                float v0 = acc[mt][nt][0] * ADJ_INV + b0;
                float v1 = acc[mt][nt][1] * ADJ_INV + b1;
                float v2 = acc[mt][nt][2] * ADJ_INV + b0;
                float v3 = acc[mt][nt][3] * ADJ_INV + b1;
                v0 = fmaxf(v0, 0.01f * v0); v1 = fmaxf(v1, 0.01f * v1);
                v2 = fmaxf(v2, 0.01f * v2); v3 = fmaxf(v3, 0.01f * v3);
                *(float2*)&dout[(size_t)r0 * HID + col]       = make_float2(v0, v1);
                *(float2*)&dout[(size_t)(r0 + 8) * HID + col] = make_float2(v2, v3);
            }
        }
        return;
    }

    // ---- layer-1 fused epilogue: h1 -> smem fp16, then y2 = h1 @ W2 -> g_yTh ----
    #pragma unroll
    for (int mt = 0; mt < 5; ++mt) {
        int lr = mt * 16 + qr;
        #pragma unroll
        for (int nt = 0; nt < 4; ++nt) {
            int col = w * 32 + nt * 8 + qc * 2;
            float b0 = bsm[col], b1 = bsm[col + 1];
            float v0 = acc[mt][nt][0] * ADJ_INV + b0;
            float v1 = acc[mt][nt][1] * ADJ_INV + b1;
            float v2 = acc[mt][nt][2] * ADJ_INV + b0;
            float v3 = acc[mt][nt][3] * ADJ_INV + b1;
            v0 = fmaxf(v0, 0.01f * v0); v1 = fmaxf(v1, 0.01f * v1);
            v2 = fmaxf(v2, 0.01f * v2); v3 = fmaxf(v3, 0.01f * v3);
            int kc = col >> 6, cc = col & 63;
            uint32_t base = H1_OFF + kc * H1_CHUNK;
            *(__half2*)(smem + base + SWZ((uint32_t)lr * 128 + cc * 2))       = __floats2half2_rn(v0, v1);
            *(__half2*)(smem + base + SWZ((uint32_t)(lr + 8) * 128 + cc * 2)) = __floats2half2_rn(v2, v3);
        }
    }
    __syncthreads();

    // 3-buffer W2 ring: fill(kc+2) issued BEFORE consume(kc); 1 sync per chunk.
    auto fillW2 = [&](int kc) {
        uint32_t dst = sb + W2B_OFF + (kc % 3) * W2B_BYTES;
        #pragma unroll
        for (int i = 0; i < 8; ++i) {
            int c = tid + i * 256;
            int row = c >> 3, ch = c & 7;
            cp_async16(dst + SWZ(row * 128 + ch * 16),
                       g_w2t + (size_t)row * HID + kc * 64 + ch * 8, 16u);
        }
        CP_COMMIT();
    };
    fillW2(0); fillW2(1);

    #pragma unroll
    for (int a = 0; a < 5; ++a)
        #pragma unroll
        for (int b = 0; b < 4; ++b)
            #pragma unroll
            for (int c = 0; c < 4; ++c) acc[a][b][c] = 0.f;

    for (int kc = 0; kc < 4; ++kc) {
        if (kc < 3) { asm volatile("cp.async.wait_group %0;" :: "n"(1)); }
        else        { asm volatile("cp.async.wait_group %0;" :: "n"(0)); }
        __syncthreads();
        if (kc + 2 < 4) fillW2(kc + 2);        // writes buffer (kc+2)%3 != kc%3
        uint32_t sa = sb + H1_OFF + kc * H1_CHUNK;
        uint32_t sB = sb + W2B_OFF + (kc % 3) * W2B_BYTES;
        #pragma unroll
        for (int ks = 0; ks < 4; ++ks) {
            uint32_t af[5][4];
            #pragma unroll
            for (int mt = 0; mt < 5; ++mt) {
                uint32_t off = (uint32_t)(mt * 16 + (lane & 15)) * 128 + ks * 32 + (lane >> 4) * 16;
                ldsm_x4(af[mt], sa + SWZ(off));
            }
            uint32_t bf[4], bf2[4];
            {
                uint32_t row = w * 32 + ((lane >> 4) & 1) * 8 + (lane & 7);
                uint32_t off = row * 128 + ks * 32 + ((lane >> 3) & 1) * 16;
                ldsm_x4(bf, sB + SWZ(off));
                uint32_t row2 = w * 32 + 16 + ((lane >> 4) & 1) * 8 + (lane & 7);
                uint32_t off2 = row2 * 128 + ks * 32 + ((lane >> 3) & 1) * 16;
                ldsm_x4(bf2, sB + SWZ(off2));
            }
            #pragma unroll
            for (int mt = 0; mt < 5; ++mt) {
                mma16816(acc[mt][0], af[mt], bf[0],  bf[1]);
                mma16816(acc[mt][1], af[mt], bf[2],  bf[3]);
                mma16816(acc[mt][2], af[mt], bf2[0], bf2[1]);
                mma16816(acc[mt][3], af[mt], bf2[2], bf2[3]);
            }
        }
    }

    // transposed y2 write (staging at Y2ST_OFF = past all 3 W2 buffers)
    __half* st = (__half*)(smem + Y2ST_OFF) + (size_t)w * 32 * 88;
    #pragma unroll
    for (int mt = 0; mt < 5; ++mt) {
        int lr = mt * 16 + qr;
        #pragma unroll
        for (int nt = 0; nt < 4; ++nt) {
            int nl = nt * 8 + qc * 2;
            st[nl * 88 + lr]           = __float2half_rn(acc[mt][nt][0]);
            st[(nl + 1) * 88 + lr]     = __float2half_rn(acc[mt][nt][1]);
            st[nl * 88 + lr + 8]       = __float2half_rn(acc[mt][nt][2]);
            st[(nl + 1) * 88 + lr + 8] = __float2half_rn(acc[mt][nt][3]);
        }
    }
    __syncwarp();
    if (lane < 20) {
        #pragma unroll 4
        for (int nl = 0; nl < 32; ++nl) {
            *(uint2*)&g_yTh[(size_t)(w * 32 + nl) * N_NODES + m0 + lane * 4] =
                *(uint2*)&st[nl * 88 + lane * 4];
        }
    }
}

// ---------------------------------------------------------------------------
extern "C" void kernel_launch(void* const* d_in, const int* in_sizes, int n_in,
                              void* d_out, int out_size) {
    (void)in_sizes; (void)n_in; (void)out_size;
    const int*   nodes = (const int*)  d_in[0];
    const float* emb   = (const float*)d_in[1];
    const float* adj   = (const float*)d_in[2];
    const float* W1    = (const float*)d_in[3];
    const float* b1    = (const float*)d_in[4];
    const float* W2    = (const float*)d_in[5];
    const float* b2    = (const float*)d_in[6];
    float* out = (float*)d_out;

    cudaFuncSetAttribute(big_gemm_kernel, cudaFuncAttributeMaxDynamicSharedMemorySize, SMEM_BYTES);
    cudaFuncSetAttribute(small_mma_kernel, cudaFuncAttributeMaxDynamicSharedMemorySize, SSMEM_BYTES);

    int gm = N_NODES / BM;                     // 125, 1 CTA/SM
    int gsm = N_NODES / SBM;                   // 125, exact

    prep_kernel<<<GB_END, 128>>>(nodes, emb, W1, W2);             // gather + W1^T + W2^T
    small_mma_kernel<<<gsm, 256, SSMEM_BYTES>>>();                // g_yTh = (x@W1)^T
    big_gemm_kernel<<<gm, 256, SMEM_BYTES>>>(adj, b1, nullptr);   // convert + h1 + y2 -> g_yTh
    big_gemm_kernel<<<gm, 256, SMEM_BYTES>>>(nullptr, b2, out);   // out = lrelu(adj@y2 + b2)
}